// round 13
// baseline (speedup 1.0000x reference)
#include <cuda_runtime.h>
#include <math.h>

#define Nn 10000
#define Ee 160000
#define Ff 4
#define Hh 32
#define Cc 4

// ---------------- scratch (device globals; no allocation allowed) -----------
__device__ float g_Qn[Nn * Hh * Hh];       // per-node Q matrices [N, H, H] (40MB)
__device__ float g_r [Nn * Hh];            // per-node b2 contribution r[n,o]
__device__ float g_xA[Nn * Hh];            // ping-pong node features (pre-relu)
__device__ float g_xB[Nn * Hh];
__device__ int    g_cnt[Nn];               // counting sort: histogram
__device__ int    g_cur[Nn];               // counting sort: scatter cursors
__device__ int    g_off[Nn + 1];           // CSR offsets by src
__device__ int    g_sdst[Ee];              // dst sorted by src
__device__ float2 g_sea [Ee];              // edge_attr sorted by src

__device__ __forceinline__ unsigned long long pack2(float a, float b) {
    float2 f = make_float2(a, b);
    return *reinterpret_cast<unsigned long long*>(&f);
}

// ---------------------------------------------------------------------------
__global__ void zero_kernel() {
    int t = blockIdx.x * blockDim.x + threadIdx.x;
    if (t < Nn) { g_cnt[t] = 0; g_cur[t] = 0; }
}

__global__ void hist_kernel(const int* __restrict__ ei) {
    int base = (blockIdx.x * blockDim.x + threadIdx.x) * 4;
#pragma unroll
    for (int j = 0; j < 4; j++) {
        int t = base + j;
        if (t < Ee) atomicAdd(&g_cnt[ei[t]], 1);
    }
}

// warp-shfl scan: 1024 threads x 10 items, 2 barriers total
__global__ void scan_kernel() {
    __shared__ int wsum[32];
    const int tid  = threadIdx.x;
    const int lane = tid & 31, wid = tid >> 5;
    const int base = tid * 10;

    int loc[10];
    int s = 0;
#pragma unroll
    for (int j = 0; j < 10; j++) {
        int idx = base + j;
        int v = (idx < Nn) ? g_cnt[idx] : 0;
        loc[j] = s;
        s += v;
    }
    int t = s;
#pragma unroll
    for (int d = 1; d < 32; d <<= 1) {
        int u = __shfl_up_sync(0xffffffffu, t, d);
        if (lane >= d) t += u;
    }
    if (lane == 31) wsum[wid] = t;
    __syncthreads();
    if (wid == 0) {
        int w = wsum[lane];
#pragma unroll
        for (int d = 1; d < 32; d <<= 1) {
            int u = __shfl_up_sync(0xffffffffu, w, d);
            if (lane >= d) w += u;
        }
        wsum[lane] = w;
    }
    __syncthreads();
    int prefix = t - s + (wid > 0 ? wsum[wid - 1] : 0);
#pragma unroll
    for (int j = 0; j < 10; j++) {
        int idx = base + j;
        if (idx < Nn) g_off[idx] = prefix + loc[j];
    }
    if (tid == 1023) g_off[Nn] = wsum[31];
}

__global__ void scatter_kernel(const int* __restrict__ ei,
                               const float* __restrict__ ea) {
    int base = (blockIdx.x * blockDim.x + threadIdx.x) * 2;
#pragma unroll
    for (int j = 0; j < 2; j++) {
        int t = base + j;
        if (t < Ee) {
            int s = ei[t];
            int p = g_off[s] + atomicAdd(&g_cur[s], 1);
            g_sdst[p] = ei[Ee + t];
            g_sea[p]  = reinterpret_cast<const float2*>(ea)[t];
        }
    }
}

// ---------------------------------------------------------------------------
// layer-0 node init: agg = x·root + bias,  rbuf = x·b2   (din = 4)
// ---------------------------------------------------------------------------
__global__ void aux0_kernel(const float* __restrict__ x,
                            const float* __restrict__ root,
                            const float* __restrict__ bias,
                            const float* __restrict__ b2,
                            float* __restrict__ agg,
                            float* __restrict__ rbuf) {
    int warp = (blockIdx.x * blockDim.x + threadIdx.x) >> 5;
    int lane = threadIdx.x & 31;
    if (warp >= Nn) return;
    float accA = 0.f, accR = 0.f;
#pragma unroll
    for (int i = 0; i < Ff; i++) {
        float xv = x[warp * Ff + i];
        accA = fmaf(xv, root[i * Hh + lane], accA);
        accR = fmaf(xv, b2[i * Hh + lane], accR);
    }
    agg [warp * Hh + lane] = accA + bias[lane];
    rbuf[warp * Hh + lane] = accR;
}

// ---------------------------------------------------------------------------
// shared edge-pair mainloop: hs2[p][k] = (hA[k], hB[k]) for edge pair p.
// qq[k] = (q[k], q[k]). One FFMA2 = MAC for two edges.
// ---------------------------------------------------------------------------
__device__ __forceinline__ void edge_pair_loop(
    int beg, int end, int lane,
    float w1a, float w1b, float b1v,
    const unsigned long long* qq,     // [32] packed (q,q)
    unsigned long long rr,            // packed (rsrc, rsrc)
    float2 (*hs2)[32],                // [16 pairs][32 k]
    float* __restrict__ agg)
{
    for (int t = beg; t < end; t += 32) {
        const int m = min(32, end - t);
        float2 eav = make_float2(0.f, 0.f);
        int dstv = 0;
        if (lane < m) { eav = g_sea[t + lane]; dstv = g_sdst[t + lane]; }

        const int mp = (m + 1) >> 1;
        // phase 1: h for both edges of each pair (lane = k)
        for (int p = 0; p < mp; p++) {
            float ea0a = __shfl_sync(0xffffffffu, eav.x, 2 * p);
            float ea1a = __shfl_sync(0xffffffffu, eav.y, 2 * p);
            float ea0b = __shfl_sync(0xffffffffu, eav.x, 2 * p + 1);
            float ea1b = __shfl_sync(0xffffffffu, eav.y, 2 * p + 1);
            float ha = fmaxf(fmaf(ea0a, w1a, fmaf(ea1a, w1b, b1v)), 0.f);
            float hb = fmaxf(fmaf(ea0b, w1a, fmaf(ea1b, w1b, b1v)), 0.f);
            hs2[p][lane] = make_float2(ha, hb);
        }
        __syncwarp();

        // phase 2: two messages per pass via f32x2
        for (int p = 0; p < mp; p++) {
            int dstA = __shfl_sync(0xffffffffu, dstv, 2 * p);
            int dstB = __shfl_sync(0xffffffffu, dstv, 2 * p + 1);
            const ulonglong2* hv = reinterpret_cast<const ulonglong2*>(hs2[p]);
            unsigned long long a0 = rr, a1 = 0ULL, a2 = 0ULL, a3 = 0ULL;
#pragma unroll
            for (int c = 0; c < 8; c++) {
                ulonglong2 u0 = hv[2 * c];
                ulonglong2 u1 = hv[2 * c + 1];
                asm("fma.rn.f32x2 %0,%1,%2,%0;" : "+l"(a0) : "l"(u0.x), "l"(qq[4 * c    ]));
                asm("fma.rn.f32x2 %0,%1,%2,%0;" : "+l"(a1) : "l"(u0.y), "l"(qq[4 * c + 1]));
                asm("fma.rn.f32x2 %0,%1,%2,%0;" : "+l"(a2) : "l"(u1.x), "l"(qq[4 * c + 2]));
                asm("fma.rn.f32x2 %0,%1,%2,%0;" : "+l"(a3) : "l"(u1.y), "l"(qq[4 * c + 3]));
            }
            unsigned long long s01, s23, stot;
            asm("add.rn.f32x2 %0,%1,%2;" : "=l"(s01)  : "l"(a0),  "l"(a1));
            asm("add.rn.f32x2 %0,%1,%2;" : "=l"(s23)  : "l"(a2),  "l"(a3));
            asm("add.rn.f32x2 %0,%1,%2;" : "=l"(stot) : "l"(s01), "l"(s23));
            float2 msg = *reinterpret_cast<float2*>(&stot);
            atomicAdd(&agg[dstA * Hh + lane], msg.x);
            if (2 * p + 1 < m)
                atomicAdd(&agg[dstB * Hh + lane], msg.y);
        }
        __syncwarp();
    }
}

// ---------------------------------------------------------------------------
// layer-0 edge kernel: qq built on the fly from 4 x-values and smem w2_0.
// ---------------------------------------------------------------------------
__global__ void edge0_kernel(const float* __restrict__ x,
                             const float* __restrict__ w1,
                             const float* __restrict__ b1,
                             const float* __restrict__ w2,
                             const float* __restrict__ rbuf,
                             float* __restrict__ agg) {
    __shared__ float w2s[Hh * Ff * Hh];        // 16KB
    __shared__ float2 hs_all[8][16][32];       // 32KB
    const int wip  = threadIdx.x >> 5;
    const int n    = (blockIdx.x * blockDim.x + threadIdx.x) >> 5;
    const int lane = threadIdx.x & 31;

    for (int i = threadIdx.x; i < Hh * Ff * Hh; i += 256)
        w2s[i] = w2[i];
    __syncthreads();

    if (n >= Nn) return;
    const int beg = g_off[n], end = g_off[n + 1];
    if (beg == end) return;

    const float w1a = w1[lane], w1b = w1[Hh + lane], b1v = b1[lane];

    float x0 = x[n * Ff + 0], x1 = x[n * Ff + 1];
    float x2 = x[n * Ff + 2], x3 = x[n * Ff + 3];
    unsigned long long qq[Hh];
#pragma unroll
    for (int k = 0; k < Hh; k++) {
        const float* w = w2s + k * (Ff * Hh) + lane;
        float qk = fmaf(x0, w[0], fmaf(x1, w[Hh],
                   fmaf(x2, w[2 * Hh], x3 * w[3 * Hh])));
        qq[k] = pack2(qk, qk);
    }
    float rsrc = rbuf[n * Hh + lane];

    edge_pair_loop(beg, end, lane, w1a, w1b, b1v, qq, pack2(rsrc, rsrc),
                   hs_all[wip], agg);
}

// ---------------------------------------------------------------------------
// fused Qn + aux (f32x2 FMA GEMM), layers 1-2 (din = 32)
// ---------------------------------------------------------------------------
template <int DIN>
__global__ void qnaux_kernel(const float* __restrict__ x,
                             const float* __restrict__ w2,
                             const float* __restrict__ root,
                             const float* __restrict__ bias,
                             const float* __restrict__ b2,
                             float* __restrict__ Qn,
                             float* __restrict__ agg,
                             float* __restrict__ rbuf) {
    __shared__ float2 xs2[8][DIN];
    const int nbase = blockIdx.x * 8;
    const int tid = threadIdx.x;

    for (int idx = tid; idx < 8 * DIN; idx += 128) {
        int t = idx / DIN, i = idx % DIN;
        float v = fmaxf(x[(nbase + t) * DIN + i], 0.f);   // relu on load
        xs2[t][i] = make_float2(v, v);
    }
    __syncthreads();

    const int c0 = tid * 8;
    const int k  = c0 >> 5;
    const int ob = c0 & 31;
    const float* wbase = w2 + k * (DIN * Hh) + ob;

    unsigned long long acc[8][4];
#pragma unroll
    for (int t = 0; t < 8; t++)
#pragma unroll
        for (int p = 0; p < 4; p++) acc[t][p] = 0ULL;

#pragma unroll
    for (int i = 0; i < DIN; i++) {
        ulonglong2 wa = *reinterpret_cast<const ulonglong2*>(wbase + i * Hh);
        ulonglong2 wb = *reinterpret_cast<const ulonglong2*>(wbase + i * Hh + 4);
#pragma unroll
        for (int t = 0; t < 8; t++) {
            unsigned long long xv =
                *reinterpret_cast<const unsigned long long*>(&xs2[t][i]);
            asm("fma.rn.f32x2 %0,%1,%2,%0;" : "+l"(acc[t][0]) : "l"(xv), "l"(wa.x));
            asm("fma.rn.f32x2 %0,%1,%2,%0;" : "+l"(acc[t][1]) : "l"(xv), "l"(wa.y));
            asm("fma.rn.f32x2 %0,%1,%2,%0;" : "+l"(acc[t][2]) : "l"(xv), "l"(wb.x));
            asm("fma.rn.f32x2 %0,%1,%2,%0;" : "+l"(acc[t][3]) : "l"(xv), "l"(wb.y));
        }
    }

#pragma unroll
    for (int t = 0; t < 8; t++) {
        float* dst = Qn + (nbase + t) * (Hh * Hh) + c0;
#pragma unroll
        for (int p = 0; p < 4; p++)
            *reinterpret_cast<unsigned long long*>(dst + p * 2) = acc[t][p];
    }

    for (int it = tid; it < 256; it += 128) {
        int t = it >> 5, o = it & 31;
        float accA = 0.f, accR = 0.f;
#pragma unroll
        for (int i = 0; i < DIN; i++) {
            float xv = xs2[t][i].x;
            accA = fmaf(xv, root[i * Hh + o], accA);
            accR = fmaf(xv, b2  [i * Hh + o], accR);
        }
        agg [(nbase + t) * Hh + o] = accA + bias[o];
        rbuf[(nbase + t) * Hh + o] = accR;
    }
}

// ---------------------------------------------------------------------------
// edge stage (layers 1-2): qq loaded from precomputed Qn.
// ---------------------------------------------------------------------------
__global__ void edge3_kernel(const float* __restrict__ w1,
                             const float* __restrict__ b1,
                             const float* __restrict__ Qn,
                             const float* __restrict__ rbuf,
                             float* __restrict__ agg) {
    __shared__ float2 hs_all[8][16][32];       // 32KB
    const int wip  = threadIdx.x >> 5;
    const int n    = (blockIdx.x * blockDim.x + threadIdx.x) >> 5;
    const int lane = threadIdx.x & 31;
    if (n >= Nn) return;
    const int beg = g_off[n], end = g_off[n + 1];
    if (beg == end) return;

    const float w1a = w1[lane], w1b = w1[Hh + lane], b1v = b1[lane];

    unsigned long long qq[Hh];
    const float* __restrict__ q = Qn + n * (Hh * Hh) + lane;
#pragma unroll
    for (int k = 0; k < Hh; k++) {
        float qk = q[k * Hh];
        qq[k] = pack2(qk, qk);
    }
    float rsrc = rbuf[n * Hh + lane];

    edge_pair_loop(beg, end, lane, w1a, w1b, b1v, qq, pack2(rsrc, rsrc),
                   hs_all[wip], agg);
}

// ---------------------------------------------------------------------------
__global__ void fc_kernel(const float* __restrict__ xr,
                          const float* __restrict__ fcw,
                          const float* __restrict__ fcb,
                          float* __restrict__ out) {
    int warp = (blockIdx.x * blockDim.x + threadIdx.x) >> 5;
    int lane = threadIdx.x & 31;
    if (warp >= Nn) return;

    float xv = fmaxf(xr[warp * Hh + lane], 0.f);
    float lg[Cc];
#pragma unroll
    for (int c = 0; c < Cc; c++) {
        float p = xv * fcw[lane * Cc + c];
#pragma unroll
        for (int s = 16; s > 0; s >>= 1)
            p += __shfl_xor_sync(0xffffffffu, p, s);
        lg[c] = p + fcb[c];
    }
    float m = fmaxf(fmaxf(lg[0], lg[1]), fmaxf(lg[2], lg[3]));
    float se = 0.f;
#pragma unroll
    for (int c = 0; c < Cc; c++) se += __expf(lg[c] - m);
    float lse = m + __logf(se);
    if (lane < Cc) out[warp * Cc + lane] = lg[lane] - lse;
}

// ---------------------------------------------------------------------------
extern "C" void kernel_launch(void* const* d_in, const int* in_sizes, int n_in,
                              void* d_out, int out_size) {
    (void)in_sizes; (void)n_in; (void)out_size;

    const float* x  = (const float*)d_in[0];
    const int*   ei = (const int*)  d_in[1];
    const float* ea = (const float*)d_in[2];
    const float* w1[3];  const float* b1[3];  const float* w2[3];
    const float* b2[3];  const float* rt[3];  const float* bs[3];
    for (int l = 0; l < 3; l++) {
        w1[l] = (const float*)d_in[3 + 6 * l + 0];
        b1[l] = (const float*)d_in[3 + 6 * l + 1];
        w2[l] = (const float*)d_in[3 + 6 * l + 2];
        b2[l] = (const float*)d_in[3 + 6 * l + 3];
        rt[l] = (const float*)d_in[3 + 6 * l + 4];
        bs[l] = (const float*)d_in[3 + 6 * l + 5];
    }
    const float* fcw = (const float*)d_in[21];
    const float* fcb = (const float*)d_in[22];
    float* out = (float*)d_out;

    float *Qn, *rbuf, *xA, *xB;
    cudaGetSymbolAddress((void**)&Qn,   g_Qn);
    cudaGetSymbolAddress((void**)&rbuf, g_r);
    cudaGetSymbolAddress((void**)&xA,   g_xA);
    cudaGetSymbolAddress((void**)&xB,   g_xB);

    const int qnBlocks       = Nn / 8;                 // 1250
    const int nodeWarpBlocks = (Nn * 32 + 255) / 256;  // 1250
    const int e2Blocks       = (Ee / 2 + 255) / 256;   // 313

    // ---------------- counting sort of edges by src ---------------------
    zero_kernel<<<(Nn + 1023) / 1024, 1024>>>();
    hist_kernel<<<(Ee / 4 + 255) / 256, 256>>>(ei);
    scan_kernel<<<1, 1024>>>();
    scatter_kernel<<<e2Blocks, 256>>>(ei, ea);

    // ---------------- layer 0: Qn folded into the edge kernel -----------
    aux0_kernel<<<nodeWarpBlocks, 256>>>(x, rt[0], bs[0], b2[0], xA, rbuf);
    edge0_kernel<<<nodeWarpBlocks, 256>>>(x, w1[0], b1[0], w2[0], rbuf, xA);

    // ---------------- layer 1 -------------------------------------------
    qnaux_kernel<Hh><<<qnBlocks, 128>>>(xA, w2[1], rt[1], bs[1], b2[1], Qn, xB, rbuf);
    edge3_kernel<<<nodeWarpBlocks, 256>>>(w1[1], b1[1], Qn, rbuf, xB);

    // ---------------- layer 2 -------------------------------------------
    qnaux_kernel<Hh><<<qnBlocks, 128>>>(xB, w2[2], rt[2], bs[2], b2[2], Qn, xA, rbuf);
    edge3_kernel<<<nodeWarpBlocks, 256>>>(w1[2], b1[2], Qn, rbuf, xA);

    // ---------------- FC + log_softmax ----------------------------------
    fc_kernel<<<nodeWarpBlocks, 256>>>(xA, fcw, fcb, out);
}